// round 4
// baseline (speedup 1.0000x reference)
#include <cuda_runtime.h>
#include <math.h>

#define B_ 128
#define T_ 1024
#define D_ 128
#define U_ 256
#define M_ 64

// Static device scratch (no cudaMalloc anywhere)
__device__ float    g_Cmem[U_ * U_];     // 0.1 * U_mem @ W_mem  [256][256]
__device__ float    g_X[134217728];      // [t][gu(1024)][b(128)] fp32 (512 MB bss)
__device__ unsigned g_sync[2];           // [0]=arrive counter, [1]=release step

// ---------------------------------------------------------------------------
// K0: Cmem[k][j] = 0.1 * sum_m U_mem[k][m] * W_mem[m][j]
// ---------------------------------------------------------------------------
__global__ void cmem_kernel(const float* __restrict__ Umem,
                            const float* __restrict__ Wmem) {
    int k = blockIdx.x;       // 0..255
    int j = threadIdx.x;      // 0..255
    float s = 0.f;
#pragma unroll
    for (int m = 0; m < M_; m++)
        s += Umem[k * M_ + m] * Wmem[m * U_ + j];
    g_Cmem[k * U_ + j] = 0.1f * s;
}

// ---------------------------------------------------------------------------
// K1: input projections. X[t][gu][b] = sum_d inp[b][t][d]*W_g[d][u] + b_g[u]
// Tile: 64 gu x 128 b per block, K = 128 full depth. 256 threads, 4x8 microtile.
// ---------------------------------------------------------------------------
#define K1_SMEM_BYTES ((128 * 68 + 128 * 129) * 4)
__global__ void __launch_bounds__(256) proj_kernel(
    const float* __restrict__ inp,
    const float* __restrict__ Wi, const float* __restrict__ Wf,
    const float* __restrict__ Wc, const float* __restrict__ Wo,
    const float* __restrict__ bi, const float* __restrict__ bf,
    const float* __restrict__ bc, const float* __restrict__ bo)
{
    extern __shared__ float sm[];
    float* Wsh = sm;               // [d=128][64] stride 68
    float* Ish = sm + 128 * 68;    // [b=128][128] stride 129

    const int t   = blockIdx.y;
    const int gu0 = blockIdx.x * 64;          // tile inside one gate (64 | 256)
    const int tid = threadIdx.x;

    const int g = gu0 >> 8;
    const float* Wg = (g == 0) ? Wi : (g == 1) ? Wf : (g == 2) ? Wc : Wo;
    const float* bv = (g == 0) ? bi : (g == 1) ? bf : (g == 2) ? bc : bo;
    const int u0 = gu0 & 255;

    for (int i = tid; i < 128 * 64; i += 256) {
        int d = i >> 6, j = i & 63;
        Wsh[d * 68 + j] = Wg[d * U_ + u0 + j];
    }
    for (int i = tid; i < 128 * 128; i += 256) {
        int b = i >> 7, d = i & 127;
        Ish[b * 129 + d] = inp[((size_t)b * T_ + t) * D_ + d];
    }
    __syncthreads();

    const int j4 = (tid & 15) * 4;     // 16 * 4 = 64 gu
    const int b8 = (tid >> 4) * 8;     // 16 * 8 = 128 b

    float acc[4][8];
#pragma unroll
    for (int jj = 0; jj < 4; jj++)
#pragma unroll
        for (int bb = 0; bb < 8; bb++) acc[jj][bb] = 0.f;

#pragma unroll 4
    for (int d = 0; d < 128; d++) {
        float4 w = *(const float4*)&Wsh[d * 68 + j4];
        float iv[8];
#pragma unroll
        for (int bb = 0; bb < 8; bb++) iv[bb] = Ish[(b8 + bb) * 129 + d];
#pragma unroll
        for (int bb = 0; bb < 8; bb++) {
            acc[0][bb] = fmaf(w.x, iv[bb], acc[0][bb]);
            acc[1][bb] = fmaf(w.y, iv[bb], acc[1][bb]);
            acc[2][bb] = fmaf(w.z, iv[bb], acc[2][bb]);
            acc[3][bb] = fmaf(w.w, iv[bb], acc[3][bb]);
        }
    }

    float* outp = g_X + ((size_t)t * 1024 + gu0) * 128;
#pragma unroll
    for (int jj = 0; jj < 4; jj++) {
        float bb_ = bv[u0 + j4 + jj];
        float4 lo = make_float4(acc[jj][0] + bb_, acc[jj][1] + bb_,
                                acc[jj][2] + bb_, acc[jj][3] + bb_);
        float4 hi = make_float4(acc[jj][4] + bb_, acc[jj][5] + bb_,
                                acc[jj][6] + bb_, acc[jj][7] + bb_);
        *(float4*)&outp[(size_t)(j4 + jj) * 128 + b8]     = lo;
        *(float4*)&outp[(size_t)(j4 + jj) * 128 + b8 + 4] = hi;
    }
}

// ---------------------------------------------------------------------------
// K2: persistent recurrence. 128 CTAs = 16 batch-groups x 8 column-slices.
// 320 threads: g = tid/64 selects matrix {Ui,Uf,Uc,Uo,Cmem}, kh = K-half,
// c = column in 32-wide slice. Each thread holds 128 weights in registers.
// Grid barrier per step (monotonic counter + release flag; memset per launch).
// ---------------------------------------------------------------------------
__global__ void __launch_bounds__(320, 1) recur_kernel(
    const float* __restrict__ Ui, const float* __restrict__ Uf,
    const float* __restrict__ Uc, const float* __restrict__ Uo,
    float* __restrict__ out)     // [B][T][U]
{
    __shared__ float sh_h[8][256];        // h_prev for this batch group
    __shared__ float sh_x[4][32][9];      // x gates [col][b], padded
    __shared__ float zbuf[2][5][8][32];   // K-half partials (mat, b, col)
    __shared__ float c_sm[8][32];         // cell state (CTA-local)
    __shared__ float r_sm[8][32];         // mem_read state (CTA-local)

    const int bg  = blockIdx.x >> 3;      // 0..15 batch group (8 rows)
    const int sl  = blockIdx.x & 7;       // 0..7  column slice (32 cols)
    const int tid = threadIdx.x;
    const int g   = tid / 64;             // 0..4
    const int kh  = (tid >> 5) & 1;       // K half
    const int c   = tid & 31;             // column within slice
    const int col = sl * 32 + c;
    const int khbase = kh * 128;

    const float* Wm = (g == 0) ? Ui : (g == 1) ? Uf : (g == 2) ? Uc :
                      (g == 3) ? Uo : g_Cmem;

    float wreg[128];
#pragma unroll
    for (int kk = 0; kk < 128; kk++)
        wreg[kk] = Wm[(size_t)(khbase + kk) * 256 + col];

    for (int i = tid; i < 256; i += 320) {
        ((float*)c_sm)[i] = 0.f;
        ((float*)r_sm)[i] = 0.f;
    }

    const unsigned NB = gridDim.x;        // 128

    for (int t = 0; t < T_; t++) {
        // stage h_prev and x
        if (t == 0) {
            for (int i = tid; i < 2048; i += 320) ((float*)sh_h)[i] = 0.f;
        } else {
            for (int i = tid; i < 2048; i += 320) {
                int b = i >> 8, k = i & 255;
                ((float*)sh_h)[i] =
                    out[((size_t)(bg * 8 + b) * T_ + (t - 1)) * U_ + k];
            }
        }
        {
            const float* xp = g_X + (size_t)t * 1024 * 128;
            for (int i = tid; i < 1024; i += 320) {
                int gg = i >> 8, u32 = (i >> 3) & 31, bb = i & 7;
                sh_x[gg][u32][bb] =
                    xp[(size_t)(gg * 256 + sl * 32 + u32) * 128 + bg * 8 + bb];
            }
        }
        __syncthreads();

        // z = h_prev @ W : one column, 8 batch rows, half K per thread
        float acc[8];
#pragma unroll
        for (int b = 0; b < 8; b++) acc[b] = 0.f;
#pragma unroll
        for (int kk = 0; kk < 128; kk += 4) {
            const float w0 = wreg[kk],     w1 = wreg[kk + 1];
            const float w2 = wreg[kk + 2], w3 = wreg[kk + 3];
#pragma unroll
            for (int b = 0; b < 8; b++) {
                float4 h4 = *(const float4*)&sh_h[b][khbase + kk];  // broadcast
                acc[b] = fmaf(h4.x, w0, acc[b]);
                acc[b] = fmaf(h4.y, w1, acc[b]);
                acc[b] = fmaf(h4.z, w2, acc[b]);
                acc[b] = fmaf(h4.w, w3, acc[b]);
            }
        }
#pragma unroll
        for (int b = 0; b < 8; b++) zbuf[kh][g][b][c] = acc[b];
        __syncthreads();

        // gates + state update: one thread per (b, col)
        if (tid < 256) {
            const int b = tid >> 5, cc = tid & 31;
            float zi = zbuf[0][0][b][cc] + zbuf[1][0][b][cc];
            float zf = zbuf[0][1][b][cc] + zbuf[1][1][b][cc];
            float zc = zbuf[0][2][b][cc] + zbuf[1][2][b][cc];
            float zo = zbuf[0][3][b][cc] + zbuf[1][3][b][cc];
            float zr = zbuf[0][4][b][cc] + zbuf[1][4][b][cc];
            float rn = r_sm[b][cc] + zr;                 // mem_read_t
            float pi = sh_x[0][cc][b] + zi + rn;
            float pf = sh_x[1][cc][b] + zf;
            float pc = sh_x[2][cc][b] + zc;
            float po = sh_x[3][cc][b] + zo;
            float ig = 1.f / (1.f + expf(-pi));
            float fg = 1.f / (1.f + expf(-pf));
            float ct = tanhf(pc);
            float og = 1.f / (1.f + expf(-po));
            float cn = fg * c_sm[b][cc] + ig * ct;
            float hv = og * tanhf(cn);
            c_sm[b][cc] = cn;
            r_sm[b][cc] = rn;
            out[((size_t)(bg * 8 + b) * T_ + t) * U_ + sl * 32 + cc] = hv;
        }
        __syncthreads();

        // grid barrier (monotonic count + release flag)
        if (tid == 0) {
            __threadfence();
            unsigned target = NB * (unsigned)(t + 1);
            unsigned old = atomicAdd(&g_sync[0], 1u);
            if (old == target - 1) {
                __threadfence();
                atomicExch(&g_sync[1], (unsigned)(t + 1));
            } else {
                volatile unsigned* rel = (volatile unsigned*)&g_sync[1];
                while (*rel < (unsigned)(t + 1)) { __nanosleep(32); }
                __threadfence();
            }
        }
        __syncthreads();
    }
}

// ---------------------------------------------------------------------------
// Launcher: capture-legal (kernel launches + one async memset, stream 0)
// ---------------------------------------------------------------------------
extern "C" void kernel_launch(void* const* d_in, const int* in_sizes, int n_in,
                              void* d_out, int out_size)
{
    const float* inp  = (const float*)d_in[0];
    const float* Wi   = (const float*)d_in[1];
    const float* Wf   = (const float*)d_in[2];
    const float* Wc   = (const float*)d_in[3];
    const float* Wo   = (const float*)d_in[4];
    const float* Uig  = (const float*)d_in[5];
    const float* Ufg  = (const float*)d_in[6];
    const float* Ucg  = (const float*)d_in[7];
    const float* Uog  = (const float*)d_in[8];
    const float* Wmem = (const float*)d_in[9];
    const float* Umem = (const float*)d_in[10];
    const float* bi   = (const float*)d_in[11];
    const float* bf   = (const float*)d_in[12];
    const float* bc   = (const float*)d_in[13];
    const float* bo   = (const float*)d_in[14];
    float* out = (float*)d_out;

    // reset barrier state (capture-legal memset node)
    void* sync_ptr = nullptr;
    cudaGetSymbolAddress(&sync_ptr, g_sync);
    cudaMemsetAsync(sync_ptr, 0, 2 * sizeof(unsigned), 0);

    cmem_kernel<<<256, 256, 0, 0>>>(Umem, Wmem);

    cudaFuncSetAttribute(proj_kernel,
                         cudaFuncAttributeMaxDynamicSharedMemorySize,
                         K1_SMEM_BYTES);
    dim3 pg(16, 1024);
    proj_kernel<<<pg, 256, K1_SMEM_BYTES, 0>>>(inp, Wi, Wf, Wc, Wo,
                                               bi, bf, bc, bo);

    recur_kernel<<<128, 320, 0, 0>>>(Uig, Ufg, Ucg, Uog, out);
}

// round 5
// speedup vs baseline: 1.1275x; 1.1275x over previous
#include <cuda_runtime.h>
#include <math.h>

#define B_ 128
#define T_ 1024
#define D_ 128
#define U_ 256
#define M_ 64

// Static device scratch (no cudaMalloc anywhere)
__device__ float g_Cmem[U_ * U_];     // 0.1 * U_mem @ W_mem  [256][256]
__device__ float g_X[134217728];      // [t][gu(1024)][b(128)] fp32

// ---------------------------------------------------------------------------
// f32x2 packed helpers (FFMA2 — only reachable via PTX fma.rn.f32x2)
// ---------------------------------------------------------------------------
__device__ __forceinline__ void fma2(unsigned long long& d,
                                     unsigned long long a,
                                     unsigned long long b) {
    asm("fma.rn.f32x2 %0, %1, %2, %0;" : "+l"(d) : "l"(a), "l"(b));
}
__device__ __forceinline__ unsigned long long pk2(float a, float b) {
    unsigned long long r;
    asm("mov.b64 %0, {%1, %2};" : "=l"(r) : "f"(a), "f"(b));
    return r;
}
__device__ __forceinline__ float sum2(unsigned long long v) {
    return __uint_as_float((unsigned)v) + __uint_as_float((unsigned)(v >> 32));
}
__device__ __forceinline__ unsigned smu32(const void* p) {
    return (unsigned)__cvta_generic_to_shared(p);
}

// ---------------------------------------------------------------------------
// K0: Cmem[k][j] = 0.1 * sum_m U_mem[k][m] * W_mem[m][j]
// ---------------------------------------------------------------------------
__global__ void cmem_kernel(const float* __restrict__ Umem,
                            const float* __restrict__ Wmem) {
    int k = blockIdx.x, j = threadIdx.x;
    float s = 0.f;
#pragma unroll
    for (int m = 0; m < M_; m++)
        s += Umem[k * M_ + m] * Wmem[m * U_ + j];
    g_Cmem[k * U_ + j] = 0.1f * s;
}

// ---------------------------------------------------------------------------
// K1: input projections, f32x2. Tile 64 gu x 128 b, K=128. 256 thr, 4x8 micro.
// ---------------------------------------------------------------------------
#define K1_SMEM_BYTES ((128 * 68 + 128 * 130) * 4)
__global__ void __launch_bounds__(256) proj_kernel(
    const float* __restrict__ inp,
    const float* __restrict__ Wi, const float* __restrict__ Wf,
    const float* __restrict__ Wc, const float* __restrict__ Wo,
    const float* __restrict__ bi, const float* __restrict__ bf,
    const float* __restrict__ bc, const float* __restrict__ bo)
{
    extern __shared__ float sm[];
    float* Wsh = sm;               // [d=128][68]
    float* Ish = sm + 128 * 68;    // [b=128][130]  (even stride -> 8B aligned pairs)

    const int t   = blockIdx.y;
    const int gu0 = blockIdx.x * 64;
    const int tid = threadIdx.x;

    const int g = gu0 >> 8;
    const float* Wg = (g == 0) ? Wi : (g == 1) ? Wf : (g == 2) ? Wc : Wo;
    const float* bv = (g == 0) ? bi : (g == 1) ? bf : (g == 2) ? bc : bo;
    const int u0 = gu0 & 255;

    for (int i = tid; i < 128 * 64; i += 256) {
        int d = i >> 6, j = i & 63;
        Wsh[d * 68 + j] = Wg[d * U_ + u0 + j];
    }
    for (int i = tid; i < 128 * 128; i += 256) {
        int b = i >> 7, d = i & 127;
        Ish[b * 130 + d] = inp[((size_t)b * T_ + t) * D_ + d];
    }
    __syncthreads();

    const int j4 = (tid & 15) * 4;
    const int b8 = (tid >> 4) * 8;

    unsigned long long acc[4][8];
#pragma unroll
    for (int jj = 0; jj < 4; jj++)
#pragma unroll
        for (int bb = 0; bb < 8; bb++) acc[jj][bb] = 0ull;

#pragma unroll 8
    for (int d = 0; d < 128; d += 2) {
        float4 wa = *(const float4*)&Wsh[d * 68 + j4];
        float4 wb = *(const float4*)&Wsh[(d + 1) * 68 + j4];
        unsigned long long w0 = pk2(wa.x, wb.x), w1 = pk2(wa.y, wb.y);
        unsigned long long w2 = pk2(wa.z, wb.z), w3 = pk2(wa.w, wb.w);
#pragma unroll
        for (int bb = 0; bb < 8; bb++) {
            unsigned long long iv =
                *(const unsigned long long*)&Ish[(b8 + bb) * 130 + d];
            fma2(acc[0][bb], w0, iv);
            fma2(acc[1][bb], w1, iv);
            fma2(acc[2][bb], w2, iv);
            fma2(acc[3][bb], w3, iv);
        }
    }

    float* outp = g_X + ((size_t)t * 1024 + gu0) * 128;
#pragma unroll
    for (int jj = 0; jj < 4; jj++) {
        float bb_ = bv[u0 + j4 + jj];
        float r[8];
#pragma unroll
        for (int bb = 0; bb < 8; bb++) r[bb] = sum2(acc[jj][bb]) + bb_;
        *(float4*)&outp[(size_t)(j4 + jj) * 128 + b8] =
            make_float4(r[0], r[1], r[2], r[3]);
        *(float4*)&outp[(size_t)(j4 + jj) * 128 + b8 + 4] =
            make_float4(r[4], r[5], r[6], r[7]);
    }
}

// ---------------------------------------------------------------------------
// K2: persistent recurrence, cluster-8. 16 clusters x 8 CTAs.
// CTA (bg, sl): 8 batch rows x 32-col slice of 5 matrices {Ui,Uf,Uc,Uo,Cmem}.
// Weights in SMEM (f32x2-paired layout). h exchanged via DSMEM push +
// barrier.cluster per step. c, r CTA-local.
// Thread map (320): g=tid/64, kq4=(tid>>4)&3 (K quarter), cp=tid&15 (col pair).
// ---------------------------------------------------------------------------
#define SMW_F4   10240                     // 5*4*16*2*16 float4 = 163840 B
#define SHH_OFF  (163840 / 4)              // [2][8][272] (K-quarter skew +4)
#define SHX_OFF  (SHH_OFF + 2 * 8 * 272)   // [4][32][9]
#define ZB_OFF   (SHX_OFF + 4 * 32 * 9)    // [4][5][8][32]
#define HST_OFF  (ZB_OFF + 4 * 5 * 8 * 32) // [8][32]
#define CSM_OFF  (HST_OFF + 256)
#define RSM_OFF  (CSM_OFF + 256)
#define R_SMEM_BYTES ((RSM_OFF + 256) * 4) // 209,408 B

__global__ void __launch_bounds__(320, 1) __cluster_dims__(8, 1, 1)
recur_kernel(const float* __restrict__ Ui, const float* __restrict__ Uf,
             const float* __restrict__ Uc, const float* __restrict__ Uo,
             float* __restrict__ out)
{
    extern __shared__ float sm[];
    float4* wsm4 = (float4*)sm;
    float*  shh  = sm + SHH_OFF;
    float*  shx  = sm + SHX_OFF;
    float*  zb   = sm + ZB_OFF;
    float*  hst  = sm + HST_OFF;
    float*  csm  = sm + CSM_OFF;
    float*  rsm  = sm + RSM_OFF;

    const int bg  = blockIdx.x >> 3;
    const int sl  = blockIdx.x & 7;
    const int tid = threadIdx.x;
    const int g   = tid / 64;
    const int r64 = tid & 63;
    const int kq4 = r64 >> 4;
    const int cp  = r64 & 15;

    // ---- load weight slices into SMEM, f32x2-paired layout ----
    // float4 idx = (((gg*4+q)*16 + j)*2 + p)*16 + lcp
    //   = { W[k][c0], W[k+1][c0], W[k][c1], W[k+1][c1] }, k = q*64+j*4+2p
    for (int idx = tid; idx < SMW_F4; idx += 320) {
        int lcp = idx & 15; int rest = idx >> 4;
        int p = rest & 1;  rest >>= 1;
        int j = rest & 15; rest >>= 4;
        int q = rest & 3;  int gg = rest >> 2;
        const float* W = (gg == 0) ? Ui : (gg == 1) ? Uf :
                         (gg == 2) ? Uc : (gg == 3) ? Uo : g_Cmem;
        int k   = q * 64 + j * 4 + 2 * p;
        int col = sl * 32 + lcp * 2;
        float4 v;
        v.x = W[(size_t)k * 256 + col];
        v.y = W[(size_t)(k + 1) * 256 + col];
        v.z = W[(size_t)k * 256 + col + 1];
        v.w = W[(size_t)(k + 1) * 256 + col + 1];
        wsm4[idx] = v;
    }
    for (int i = tid; i < 256; i += 320) { csm[i] = 0.f; rsm[i] = 0.f; }
    for (int i = tid; i < 2 * 8 * 272; i += 320) shh[i] = 0.f;
    {   // stage x for t = 0
        const float* xp = g_X;
        for (int i = tid; i < 1024; i += 320) {
            int gg = i >> 8, u32 = (i >> 3) & 31, bb = i & 7;
            shx[(gg * 32 + u32) * 9 + bb] =
                xp[(size_t)(gg * 256 + sl * 32 + u32) * 128 + bg * 8 + bb];
        }
    }
    __syncthreads();
    asm volatile("barrier.cluster.arrive.aligned;" ::: "memory");
    asm volatile("barrier.cluster.wait.aligned;" ::: "memory");

    const unsigned shh_u = smu32(shh);
    const float4*  wp    = wsm4 + (g * 4 + kq4) * 512 + cp;

    for (int t = 0; t < T_; t++) {
        const int cur = t & 1, nxt = cur ^ 1;
        const float* hcur = shh + cur * (8 * 272);

        // ---- z = h_prev @ W (2 cols, 64 K, 8 b per thread; f32x2) ----
        unsigned long long a0[8], a1[8];
#pragma unroll
        for (int b = 0; b < 8; b++) { a0[b] = 0ull; a1[b] = 0ull; }
#pragma unroll
        for (int j = 0; j < 16; j++) {
            ulonglong2 wa = *(const ulonglong2*)(wp + (j * 2 + 0) * 16);
            ulonglong2 wb = *(const ulonglong2*)(wp + (j * 2 + 1) * 16);
            const int kb = kq4 * 68 + j * 4;     // physical (skewed) k base
#pragma unroll
            for (int b = 0; b < 8; b++) {
                ulonglong2 hh = *(const ulonglong2*)(hcur + b * 272 + kb);
                fma2(a0[b], wa.x, hh.x); fma2(a1[b], wa.y, hh.x);
                fma2(a0[b], wb.x, hh.y); fma2(a1[b], wb.y, hh.y);
            }
        }
        {
            float* z = zb + (kq4 * 5 + g) * 256;
#pragma unroll
            for (int b = 0; b < 8; b++) {
                z[b * 32 + cp * 2]     = sum2(a0[b]);
                z[b * 32 + cp * 2 + 1] = sum2(a1[b]);
            }
        }
        __syncthreads();

        // ---- gates + state (one thread per (b, col)) ----
        if (tid < 256) {
            const int b = tid >> 5, cc = tid & 31;
            float zi = 0, zf = 0, zc = 0, zo = 0, zr = 0;
#pragma unroll
            for (int q = 0; q < 4; q++) {
                const float* zq = zb + q * 1280;
                zi += zq[(0 * 8 + b) * 32 + cc];
                zf += zq[(1 * 8 + b) * 32 + cc];
                zc += zq[(2 * 8 + b) * 32 + cc];
                zo += zq[(3 * 8 + b) * 32 + cc];
                zr += zq[(4 * 8 + b) * 32 + cc];
            }
            float rn = rsm[b * 32 + cc] + zr;
            float pi = shx[(0 * 32 + cc) * 9 + b] + zi + rn;
            float pf = shx[(1 * 32 + cc) * 9 + b] + zf;
            float pc = shx[(2 * 32 + cc) * 9 + b] + zc;
            float po = shx[(3 * 32 + cc) * 9 + b] + zo;
            float ig = __fdividef(1.f, 1.f + __expf(-pi));
            float fg = __fdividef(1.f, 1.f + __expf(-pf));
            float ct = __fdividef(2.f, 1.f + __expf(-2.f * pc)) - 1.f;
            float og = __fdividef(1.f, 1.f + __expf(-po));
            float cn = fg * csm[b * 32 + cc] + ig * ct;
            float hv = og * (__fdividef(2.f, 1.f + __expf(-2.f * cn)) - 1.f);
            csm[b * 32 + cc] = cn;
            rsm[b * 32 + cc] = rn;
            hst[b * 32 + cc] = hv;
            out[((size_t)(bg * 8 + b) * T_ + t) * U_ + sl * 32 + cc] = hv;
        }
        __syncthreads();

        // ---- push h slice to all 8 CTAs' shh[nxt] via DSMEM ----
        {
            const unsigned dstbuf = shh_u + (unsigned)(nxt * (8 * 272 * 4));
            const float4* h4 = (const float4*)hst;
            for (int i = tid; i < 512; i += 320) {
                int peer = i >> 6, q = i & 63;
                float4 v = h4[q];
                int b  = q >> 3, c4 = (q & 7) * 4;
                int col = sl * 32 + c4;
                unsigned dst = dstbuf +
                    (unsigned)((b * 272 + col + (col >> 6) * 4) * 4);
                unsigned ra;
                asm("mapa.shared::cluster.u32 %0, %1, %2;"
                    : "=r"(ra) : "r"(dst), "r"(peer));
                asm volatile(
                    "st.shared::cluster.v4.b32 [%0], {%1,%2,%3,%4};"
                    :: "r"(ra),
                       "r"(__float_as_uint(v.x)), "r"(__float_as_uint(v.y)),
                       "r"(__float_as_uint(v.z)), "r"(__float_as_uint(v.w))
                    : "memory");
            }
        }
        asm volatile("barrier.cluster.arrive.aligned;" ::: "memory");
        // overlap: stage x for t+1 while waiting on peers
        if (t + 1 < T_) {
            const float* xp = g_X + (size_t)(t + 1) * 1024 * 128;
            for (int i = tid; i < 1024; i += 320) {
                int gg = i >> 8, u32 = (i >> 3) & 31, bb = i & 7;
                shx[(gg * 32 + u32) * 9 + bb] =
                    xp[(size_t)(gg * 256 + sl * 32 + u32) * 128 + bg * 8 + bb];
            }
        }
        asm volatile("barrier.cluster.wait.aligned;" ::: "memory");
    }
}

// ---------------------------------------------------------------------------
// Launcher: capture-legal (kernel launches only, default stream)
// ---------------------------------------------------------------------------
extern "C" void kernel_launch(void* const* d_in, const int* in_sizes, int n_in,
                              void* d_out, int out_size)
{
    const float* inp  = (const float*)d_in[0];
    const float* Wi   = (const float*)d_in[1];
    const float* Wf   = (const float*)d_in[2];
    const float* Wc   = (const float*)d_in[3];
    const float* Wo   = (const float*)d_in[4];
    const float* Uig  = (const float*)d_in[5];
    const float* Ufg  = (const float*)d_in[6];
    const float* Ucg  = (const float*)d_in[7];
    const float* Uog  = (const float*)d_in[8];
    const float* Wmem = (const float*)d_in[9];
    const float* Umem = (const float*)d_in[10];
    const float* bi   = (const float*)d_in[11];
    const float* bf   = (const float*)d_in[12];
    const float* bc   = (const float*)d_in[13];
    const float* bo   = (const float*)d_in[14];
    float* out = (float*)d_out;

    cmem_kernel<<<256, 256, 0, 0>>>(Umem, Wmem);

    cudaFuncSetAttribute(proj_kernel,
                         cudaFuncAttributeMaxDynamicSharedMemorySize,
                         K1_SMEM_BYTES);
    dim3 pg(16, 1024);
    proj_kernel<<<pg, 256, K1_SMEM_BYTES, 0>>>(inp, Wi, Wf, Wc, Wo,
                                               bi, bf, bc, bo);

    cudaFuncSetAttribute(recur_kernel,
                         cudaFuncAttributeMaxDynamicSharedMemorySize,
                         R_SMEM_BYTES);
    recur_kernel<<<128, 320, R_SMEM_BYTES, 0>>>(Uig, Ufg, Ucg, Uog, out);
}